// round 8
// baseline (speedup 1.0000x reference)
#include <cuda_runtime.h>

#define NATOM 24
#define NSP 4
#define OUTW 384          // 64 radial + 320 angular
#define RADW 64
#define CPB 6             // centers per block
#define PARTS 4
#define THREADS 256       // 8 warps
#define NWARP 8
#define MAXTRI (CPB * 253)   // C(23,2) worst case per center

__constant__ float COSZ[8] = {
     0.980785280403230449f,  0.831469612302545237f,  0.555570233019602225f,  0.195090322016128268f,
    -0.195090322016128268f, -0.555570233019602225f, -0.831469612302545237f, -0.980785280403230449f };
__constant__ float SINZ[8] = {
     0.195090322016128268f,  0.555570233019602225f,  0.831469612302545237f,  0.980785280403230449f,
     0.980785280403230449f,  0.831469612302545237f,  0.555570233019602225f,  0.195090322016128268f };

__global__ __launch_bounds__(THREADS)
void aev_kernel(const int* __restrict__ g_species,
                const float* __restrict__ g_coords,
                float* __restrict__ g_out, int M)
{
    const int bid   = blockIdx.x;
    const int m     = bid >> 2;
    const int ibase = (bid & 3) * CPB;

    __shared__ float    sc[NATOM][3];
    __shared__ int      ssp[NATOM];
    __shared__ float    sd  [CPB][NATOM];     // dist (radial)
    __shared__ float    sfcr[CPB][NATOM];     // radial cutoff
    __shared__ float4   cu  [CPB * NATOM];    // compacted: ux,uy,uz,d
    __shared__ float    cfa [CPB * NATOM];    // compacted: fca
    __shared__ int      csp [CPB * NATOM];    // compacted: species
    __shared__ int      snn [CPB];
    __shared__ unsigned triples[MAXTRI];      // packed (off<<16)|(ia<<8)|ib
    __shared__ int      tcnt;
    __shared__ float    acc [CPB][OUTW];      // 9.2 KB

    const int tid  = threadIdx.x;
    const int lane = tid & 31;
    const int w    = tid >> 5;

    // ---- init ----------------------------------------------------------
    if (tid == 0) tcnt = 0;
    if (tid < NATOM) {
        ssp[tid]   = g_species[m * NATOM + tid];
        sc[tid][0] = g_coords[(m * NATOM + tid) * 3 + 0];
        sc[tid][1] = g_coords[(m * NATOM + tid) * 3 + 1];
        sc[tid][2] = g_coords[(m * NATOM + tid) * 3 + 2];
    }
    for (int idx = tid; idx < CPB * OUTW; idx += THREADS)
        ((float*)acc)[idx] = 0.0f;
    __syncthreads();

    // ---- warps 0..5: screen/compact + radial + emit triples -------------
    if (w < CPB) {
        const int ic = ibase + w;

        // screen (lane = neighbor j)
        bool  live = false;
        float fca = 0.f, d = 1.f, dx = 0.f, dy = 0.f, dz = 0.f;
        if (lane < NATOM) {
            int j = lane;
            dx = sc[j][0] - sc[ic][0];
            dy = sc[j][1] - sc[ic][1];
            dz = sc[j][2] - sc[ic][2];
            float d2 = dx * dx + dy * dy + dz * dz;
            bool ok = (j != ic);
            d = ok ? sqrtf(d2) : 1.0f;
            fca       = (ok && d <= 3.5f) ? (0.5f * __cosf(0.897597901025655210f * d) + 0.5f) : 0.0f;
            float fcr = (ok && d <= 5.2f) ? (0.5f * __cosf(0.604152493782718100f * d) + 0.5f) : 0.0f;
            sd[w][j]   = d;
            sfcr[w][j] = fcr;
            live = (fca > 0.0f);
        }
        unsigned mask = __ballot_sync(0xffffffffu, live);
        int nn = __popc(mask);
        if (live) {
            int pos = __popc(mask & ((1u << lane) - 1u));
            float rd = 1.0f / d;
            cu [w * NATOM + pos] = make_float4(dx * rd, dy * rd, dz * rd, d);
            cfa[w * NATOM + pos] = fca;
            csp[w * NATOM + pos] = ssp[lane];
        }
        snn[w] = nn;
        __syncwarp();

        // radial: lanes (r = lane&15), two neighbors per iteration
        {
            int   r    = lane & 15;
            int   half = lane >> 4;
            float shfr = 0.9f + 0.26875f * (float)r;
            #pragma unroll
            for (int it = 0; it < 12; it++) {
                int   j   = it * 2 + half;
                float fcr = sfcr[w][j];
                if (fcr > 0.0f) {
                    float u = sd[w][j] - shfr;
                    float v = 0.25f * fcr * __expf(-16.0f * u * u);
                    atomicAdd(&acc[w][ssp[j] * 16 + r], v);
                }
            }
        }

        // emit triples with precomputed acc offset
        int npairs = (nn * (nn - 1)) >> 1;
        int base = 0;
        if (lane == 0 && npairs > 0) base = atomicAdd(&tcnt, npairs);
        base = __shfl_sync(0xffffffffu, base, 0);
        for (int idx = lane; idx < npairs; idx += 32) {
            // decode triangular index -> (a, b)
            int a = 0, rem = idx, rowlen = nn - 1;
            while (rem >= rowlen) { rem -= rowlen; rowlen--; a++; }
            int b = a + 1 + rem;
            int ia = w * NATOM + a, ib = w * NATOM + b;
            int spa = csp[ia], spb = csp[ib];
            int lo = min(spa, spb), hi = max(spa, spb);
            int pidx = lo * NSP - ((lo * (lo - 1)) >> 1) + (hi - lo);
            unsigned off = (unsigned)(w * OUTW + RADW + pidx * 32);
            triples[base + idx] = (off << 16) | ((unsigned)ia << 8) | (unsigned)ib;
        }
    }
    __syncthreads();

    // ---- all 8 warps: drain triple list (balanced) ----------------------
    {
        const int   a_l  = lane >> 3;
        const int   z_l  = lane & 7;
        const float czc  = 0.5f * COSZ[z_l];
        const float szc  = 0.5f * SINZ[z_l];
        const float shfa = 0.9f + 0.65f * (float)a_l;
        const int   n    = tcnt;
        float* accf = (float*)acc;

        for (int t = w; t < n; t += NWARP) {
            unsigned tw = triples[t];
            int ib  = (int)(tw & 255u);
            int ia  = (int)((tw >> 8) & 255u);
            int off = (int)(tw >> 16);
            float4 ua = cu[ia];
            float4 ub = cu[ib];
            float  fa = cfa[ia];
            float  fb = cfa[ib];
            float c    = 0.95f * (ua.x * ub.x + ua.y * ub.y + ua.z * ub.z);
            float s    = sqrtf(fmaxf(0.0f, 1.0f - c * c));
            float davg = 0.5f * (ua.w + ub.w);
            float w2   = 2.0f * fa * fb;
            float cz = 0.5f + c * czc + s * szc;
            float x = cz * cz;   // ^2
            x = x * x;           // ^4
            x = x * x;           // ^8
            x = x * x;           // ^16
            x = x * x;           // ^32
            float u   = davg - shfa;
            float val = w2 * x * __expf(-8.0f * u * u);
            atomicAdd(&accf[off + a_l * 8 + z_l], val);
        }
    }
    __syncthreads();

    // ---- writeout --------------------------------------------------------
    const float* src = (const float*)acc;
    float* dstg = g_out + ((size_t)m * NATOM + ibase) * OUTW;
    for (int idx = tid; idx < CPB * OUTW; idx += THREADS)
        dstg[idx] = src[idx];
}

extern "C" void kernel_launch(void* const* d_in, const int* in_sizes, int n_in,
                              void* d_out, int out_size)
{
    const int*   species = (const int*)d_in[0];
    const float* coords  = (const float*)d_in[1];
    int M = in_sizes[0] / NATOM;
    aev_kernel<<<M * PARTS, THREADS>>>(species, coords, (float*)d_out, M);
}

// round 9
// speedup vs baseline: 1.9439x; 1.9439x over previous
#include <cuda_runtime.h>

#define NATOM 24
#define NSP 4
#define OUTW 384          // 64 radial + 320 angular
#define RADW 64
#define CPB 6             // centers per block
#define PARTS 4
#define THREADS 256       // 8 warps
#define NWARP 8
#define MAXTRI (CPB * 253)   // C(23,2) worst case per center

__constant__ float COSZ[8] = {
     0.980785280403230449f,  0.831469612302545237f,  0.555570233019602225f,  0.195090322016128268f,
    -0.195090322016128268f, -0.555570233019602225f, -0.831469612302545237f, -0.980785280403230449f };
__constant__ float SINZ[8] = {
     0.195090322016128268f,  0.555570233019602225f,  0.831469612302545237f,  0.980785280403230449f,
     0.980785280403230449f,  0.831469612302545237f,  0.555570233019602225f,  0.195090322016128268f };

__global__ __launch_bounds__(THREADS)
void aev_kernel(const int* __restrict__ g_species,
                const float* __restrict__ g_coords,
                float* __restrict__ g_out, int M)
{
    const int bid   = blockIdx.x;
    const int m     = bid >> 2;
    const int ibase = (bid & 3) * CPB;

    __shared__ float    sc[NATOM][3];
    __shared__ int      ssp[NATOM];
    __shared__ float    sd  [CPB][NATOM];
    __shared__ float    sfcr[CPB][NATOM];
    __shared__ float4   cu  [CPB * NATOM];    // compacted: ux,uy,uz,d
    __shared__ float    cfa [CPB * NATOM];    // compacted: fca
    __shared__ int      csp [CPB * NATOM];    // compacted: species
    __shared__ unsigned triples[MAXTRI];      // (off<<16)|(ia<<8)|ib
    __shared__ int      tcnt;
    __shared__ float4   st1[NWARP][32];       // c, s, off(bits), pad
    __shared__ float4   st2[NWARP][32];       // wf[0..3]
    __shared__ float    acc[CPB][OUTW];

    const int tid  = threadIdx.x;
    const int lane = tid & 31;
    const int w    = tid >> 5;

    // ---- init ----------------------------------------------------------
    if (tid == 0) tcnt = 0;
    if (tid < NATOM) {
        ssp[tid]   = g_species[m * NATOM + tid];
        sc[tid][0] = g_coords[(m * NATOM + tid) * 3 + 0];
        sc[tid][1] = g_coords[(m * NATOM + tid) * 3 + 1];
        sc[tid][2] = g_coords[(m * NATOM + tid) * 3 + 2];
    }
    for (int idx = tid; idx < CPB * OUTW; idx += THREADS)
        ((float*)acc)[idx] = 0.0f;
    __syncthreads();

    // ---- warps 0..5: screen/compact + radial + emit triples -------------
    if (w < CPB) {
        const int ic = ibase + w;

        bool  live = false;
        float fca = 0.f, d = 1.f, dx = 0.f, dy = 0.f, dz = 0.f;
        if (lane < NATOM) {
            int j = lane;
            dx = sc[j][0] - sc[ic][0];
            dy = sc[j][1] - sc[ic][1];
            dz = sc[j][2] - sc[ic][2];
            float d2 = dx * dx + dy * dy + dz * dz;
            bool ok = (j != ic);
            d = ok ? sqrtf(d2) : 1.0f;
            fca       = (ok && d <= 3.5f) ? (0.5f * __cosf(0.897597901025655210f * d) + 0.5f) : 0.0f;
            float fcr = (ok && d <= 5.2f) ? (0.5f * __cosf(0.604152493782718100f * d) + 0.5f) : 0.0f;
            sd[w][j]   = d;
            sfcr[w][j] = fcr;
            live = (fca > 0.0f);
        }
        unsigned mask = __ballot_sync(0xffffffffu, live);
        int nn = __popc(mask);
        if (live) {
            int pos = __popc(mask & ((1u << lane) - 1u));
            float rd = 1.0f / d;
            cu [w * NATOM + pos] = make_float4(dx * rd, dy * rd, dz * rd, d);
            cfa[w * NATOM + pos] = fca;
            csp[w * NATOM + pos] = ssp[lane];
        }
        __syncwarp();

        // radial
        {
            int   r    = lane & 15;
            int   half = lane >> 4;
            float shfr = 0.9f + 0.26875f * (float)r;
            #pragma unroll
            for (int it = 0; it < 12; it++) {
                int   j   = it * 2 + half;
                float fcr = sfcr[w][j];
                if (fcr > 0.0f) {
                    float u = sd[w][j] - shfr;
                    float v = 0.25f * fcr * __expf(-16.0f * u * u);
                    atomicAdd(&acc[w][ssp[j] * 16 + r], v);
                }
            }
        }

        // emit triples (precompute acc offset incl. pair-species index)
        int npairs = (nn * (nn - 1)) >> 1;
        int base = 0;
        if (lane == 0 && npairs > 0) base = atomicAdd(&tcnt, npairs);
        base = __shfl_sync(0xffffffffu, base, 0);
        for (int idx = lane; idx < npairs; idx += 32) {
            int a = 0, rem = idx, rowlen = nn - 1;
            while (rem >= rowlen) { rem -= rowlen; rowlen--; a++; }
            int b = a + 1 + rem;
            int ia = w * NATOM + a, ib = w * NATOM + b;
            int spa = csp[ia], spb = csp[ib];
            int lo = min(spa, spb), hi = max(spa, spb);
            int pidx = lo * NSP - ((lo * (lo - 1)) >> 1) + (hi - lo);
            unsigned off = (unsigned)(w * OUTW + RADW + pidx * 32);
            triples[base + idx] = (off << 16) | ((unsigned)ia << 8) | (unsigned)ib;
        }
    }
    __syncthreads();

    // ---- all warps: batched two-phase drain ------------------------------
    {
        const float czc = 0.5f * COSZ[lane & 7];
        const float szc = 0.5f * SINZ[lane & 7];
        const int   n   = tcnt;
        const int   sel = lane >> 3;     // which wf component this lane uses
        float* accf = (float*)acc;

        for (int base = w * 32; base < n; base += NWARP * 32) {
            // phase A: lane = triple
            int tg = base + lane;
            float c = 0.f, s = 0.f;
            int   off = 0;
            float4 wf = make_float4(0.f, 0.f, 0.f, 0.f);
            if (tg < n) {
                unsigned tw = triples[tg];
                int ib = (int)(tw & 255u);
                int ia = (int)((tw >> 8) & 255u);
                off = (int)(tw >> 16);
                float4 ua = cu[ia];
                float4 ub = cu[ib];
                c = 0.95f * (ua.x * ub.x + ua.y * ub.y + ua.z * ub.z);
                s = sqrtf(fmaxf(0.0f, 1.0f - c * c));
                float davg = 0.5f * (ua.w + ub.w);
                float w2   = 2.0f * cfa[ia] * cfa[ib];
                float u0 = davg - 0.90f;
                float u1 = davg - 1.55f;
                float u2 = davg - 2.20f;
                float u3 = davg - 2.85f;
                wf.x = w2 * __expf(-8.0f * u0 * u0);
                wf.y = w2 * __expf(-8.0f * u1 * u1);
                wf.z = w2 * __expf(-8.0f * u2 * u2);
                wf.w = w2 * __expf(-8.0f * u3 * u3);
            }
            st1[w][lane] = make_float4(c, s, __int_as_float(off), 0.f);
            st2[w][lane] = wf;
            __syncwarp();

            // phase B: lane = output element; padded entries are exact no-ops
            #pragma unroll
            for (int tt = 0; tt < 32; tt++) {
                float4 q  = st1[w][tt];
                float  wv = ((const float*)&st2[w][tt])[sel];
                float cz = 0.5f + q.x * czc + q.y * szc;
                float x = cz * cz;   // ^2
                x = x * x;           // ^4
                x = x * x;           // ^8
                x = x * x;           // ^16
                x = x * x;           // ^32
                atomicAdd(&accf[__float_as_int(q.z) + lane], x * wv);
            }
            __syncwarp();
        }
    }
    __syncthreads();

    // ---- writeout (float4) ----------------------------------------------
    {
        const float4* src = (const float4*)acc;
        float4* dstg = (float4*)(g_out + ((size_t)m * NATOM + ibase) * OUTW);
        #pragma unroll
        for (int idx = tid; idx < CPB * OUTW / 4; idx += THREADS)
            dstg[idx] = src[idx];
    }
}

extern "C" void kernel_launch(void* const* d_in, const int* in_sizes, int n_in,
                              void* d_out, int out_size)
{
    const int*   species = (const int*)d_in[0];
    const float* coords  = (const float*)d_in[1];
    int M = in_sizes[0] / NATOM;
    aev_kernel<<<M * PARTS, THREADS>>>(species, coords, (float*)d_out, M);
}

// round 10
// speedup vs baseline: 1.9697x; 1.0133x over previous
#include <cuda_runtime.h>

#define NATOM 24
#define NSP 4
#define OUTW 384          // 64 radial + 320 angular
#define RADW 64
#define CPB 6             // centers per block
#define PARTS 4
#define THREADS 256       // 8 warps
#define NWARP 8
#define MAXTRI (CPB * 253)
#define CHUNK 256         // staging capacity (triples per chunk)

__constant__ float COSZ[8] = {
     0.980785280403230449f,  0.831469612302545237f,  0.555570233019602225f,  0.195090322016128268f,
    -0.195090322016128268f, -0.555570233019602225f, -0.831469612302545237f, -0.980785280403230449f };
__constant__ float SINZ[8] = {
     0.195090322016128268f,  0.555570233019602225f,  0.831469612302545237f,  0.980785280403230449f,
     0.980785280403230449f,  0.831469612302545237f,  0.555570233019602225f,  0.195090322016128268f };

__global__ __launch_bounds__(THREADS)
void aev_kernel(const int* __restrict__ g_species,
                const float* __restrict__ g_coords,
                float* __restrict__ g_out, int M)
{
    const int bid   = blockIdx.x;
    const int m     = bid >> 2;
    const int ibase = (bid & 3) * CPB;

    __shared__ float    sc[NATOM][3];
    __shared__ int      ssp[NATOM];
    __shared__ float    sd  [CPB][NATOM];
    __shared__ float    sfcr[CPB][NATOM];
    __shared__ float4   cu  [CPB * NATOM];    // compacted: ux,uy,uz,d
    __shared__ float    cfa [CPB * NATOM];    // compacted: fca
    __shared__ int      csp [CPB * NATOM];    // compacted: species
    __shared__ unsigned triples[MAXTRI];      // (off<<16)|(ia<<8)|ib
    __shared__ int      tcnt;
    __shared__ float4   st1[CHUNK];           // c, s, off(bits), pad
    __shared__ float4   st2[CHUNK];           // folded weights wf[0..3]
    __shared__ float    acc[CPB][OUTW];

    const int tid  = threadIdx.x;
    const int lane = tid & 31;
    const int w    = tid >> 5;

    // ---- init ----------------------------------------------------------
    if (tid == 0) tcnt = 0;
    if (tid < NATOM) {
        ssp[tid]   = g_species[m * NATOM + tid];
        sc[tid][0] = g_coords[(m * NATOM + tid) * 3 + 0];
        sc[tid][1] = g_coords[(m * NATOM + tid) * 3 + 1];
        sc[tid][2] = g_coords[(m * NATOM + tid) * 3 + 2];
    }
    for (int idx = tid; idx < CPB * OUTW; idx += THREADS)
        ((float*)acc)[idx] = 0.0f;
    __syncthreads();

    // ---- warps 0..5: screen/compact + radial + emit triples -------------
    if (w < CPB) {
        const int ic = ibase + w;

        bool  live = false;
        float fca = 0.f, d = 1.f, dx = 0.f, dy = 0.f, dz = 0.f;
        if (lane < NATOM) {
            int j = lane;
            dx = sc[j][0] - sc[ic][0];
            dy = sc[j][1] - sc[ic][1];
            dz = sc[j][2] - sc[ic][2];
            float d2 = dx * dx + dy * dy + dz * dz;
            bool ok = (j != ic);
            d = ok ? sqrtf(d2) : 1.0f;
            fca       = (ok && d <= 3.5f) ? (0.5f * __cosf(0.897597901025655210f * d) + 0.5f) : 0.0f;
            float fcr = (ok && d <= 5.2f) ? (0.5f * __cosf(0.604152493782718100f * d) + 0.5f) : 0.0f;
            sd[w][j]   = d;
            sfcr[w][j] = fcr;
            live = (fca > 0.0f);
        }
        unsigned mask = __ballot_sync(0xffffffffu, live);
        int nn = __popc(mask);
        if (live) {
            int pos = __popc(mask & ((1u << lane) - 1u));
            float rd = 1.0f / d;
            cu [w * NATOM + pos] = make_float4(dx * rd, dy * rd, dz * rd, d);
            cfa[w * NATOM + pos] = fca;
            csp[w * NATOM + pos] = ssp[lane];
        }
        __syncwarp();

        // radial
        {
            int   r    = lane & 15;
            int   half = lane >> 4;
            float shfr = 0.9f + 0.26875f * (float)r;
            #pragma unroll
            for (int it = 0; it < 12; it++) {
                int   j   = it * 2 + half;
                float fcr = sfcr[w][j];
                if (fcr > 0.0f) {
                    float u = sd[w][j] - shfr;
                    float v = 0.25f * fcr * __expf(-16.0f * u * u);
                    atomicAdd(&acc[w][ssp[j] * 16 + r], v);
                }
            }
        }

        // emit triples (precompute acc offset incl. pair-species index)
        int npairs = (nn * (nn - 1)) >> 1;
        int base = 0;
        if (lane == 0 && npairs > 0) base = atomicAdd(&tcnt, npairs);
        base = __shfl_sync(0xffffffffu, base, 0);
        for (int idx = lane; idx < npairs; idx += 32) {
            int a = 0, rem = idx, rowlen = nn - 1;
            while (rem >= rowlen) { rem -= rowlen; rowlen--; a++; }
            int b = a + 1 + rem;
            int ia = w * NATOM + a, ib = w * NATOM + b;
            int spa = csp[ia], spb = csp[ib];
            int lo = min(spa, spb), hi = max(spa, spb);
            int pidx = lo * NSP - ((lo * (lo - 1)) >> 1) + (hi - lo);
            unsigned off = (unsigned)(w * OUTW + RADW + pidx * 32);
            triples[base + idx] = (off << 16) | ((unsigned)ia << 8) | (unsigned)ib;
        }
    }
    __syncthreads();

    // ---- block-wide two-phase drain --------------------------------------
    {
        const float czc = 0.5f * COSZ[lane & 7];
        const float szc = 0.5f * SINZ[lane & 7];
        const int   n   = tcnt;
        const int   sel = lane >> 3;
        float* accf = (float*)acc;

        for (int chunk = 0; chunk < n; chunk += CHUNK) {
            const int cnt = min(CHUNK, n - chunk);

            // phase A: thread = triple (whole block stages in one pass)
            int tg = chunk + tid;
            if (tid < cnt) {
                unsigned tw = triples[tg];
                int ib  = (int)(tw & 255u);
                int ia  = (int)((tw >> 8) & 255u);
                int off = (int)(tw >> 16);
                float4 ua = cu[ia];
                float4 ub = cu[ib];
                float c = 0.95f * (ua.x * ub.x + ua.y * ub.y + ua.z * ub.z);
                float s = sqrtf(fmaxf(0.0f, 1.0f - c * c));
                float davg = 0.5f * (ua.w + ub.w);
                float w2   = 2.0f * cfa[ia] * cfa[ib];
                float u0 = davg - 0.90f;
                float u1 = davg - 1.55f;
                float u2 = davg - 2.20f;
                float u3 = davg - 2.85f;
                float4 wf;
                wf.x = w2 * __expf(-8.0f * u0 * u0);
                wf.y = w2 * __expf(-8.0f * u1 * u1);
                wf.z = w2 * __expf(-8.0f * u2 * u2);
                wf.w = w2 * __expf(-8.0f * u3 * u3);
                st1[tid] = make_float4(c, s, __int_as_float(off), 0.f);
                st2[tid] = wf;
            }
            __syncthreads();

            // phase B: warp = triple, round-robin granularity 1 (balanced)
            for (int t = w; t < cnt; t += NWARP) {
                float4 q  = st1[t];
                float  wv = ((const float*)&st2[t])[sel];
                float cz = 0.5f + q.x * czc + q.y * szc;
                float x = cz * cz;   // ^2
                x = x * x;           // ^4
                x = x * x;           // ^8
                x = x * x;           // ^16
                x = x * x;           // ^32
                atomicAdd(&accf[__float_as_int(q.z) + lane], x * wv);
            }
            __syncthreads();
        }
    }

    // ---- writeout (float4) ----------------------------------------------
    {
        const float4* src = (const float4*)acc;
        float4* dstg = (float4*)(g_out + ((size_t)m * NATOM + ibase) * OUTW);
        #pragma unroll
        for (int idx = tid; idx < CPB * OUTW / 4; idx += THREADS)
            dstg[idx] = src[idx];
    }
}

extern "C" void kernel_launch(void* const* d_in, const int* in_sizes, int n_in,
                              void* d_out, int out_size)
{
    const int*   species = (const int*)d_in[0];
    const float* coords  = (const float*)d_in[1];
    int M = in_sizes[0] / NATOM;
    aev_kernel<<<M * PARTS, THREADS>>>(species, coords, (float*)d_out, M);
}